// round 1
// baseline (speedup 1.0000x reference)
#include <cuda_runtime.h>
#include <math.h>

#define D     256
#define NBANK 512
#define TM    64        // queries per block
#define TN    128       // n-chunk (gemm1) / d-chunk (gemm2)
#define TK    32        // k-chunk
#define SLD   520       // sim row stride (floats), padded
#define BLD   132       // B-tile row stride (floats), padded, %4==0
#define ALD   36        // A-tile row stride (floats), padded, %4==0

// SMEM layout (floats): S[TM*SLD] | At[TM*ALD] | Bt[TK*BLD] | rinv[TM] | rsum[TM]
#define SMEM_FLOATS (TM*SLD + TM*ALD + TK*BLD + TM + TM)
#define SMEM_BYTES  (SMEM_FLOATS * 4)

// Normalized bank scratch (allowed: __device__ global, no allocation)
__device__ float g_embn[NBANK * D];

__global__ void norm_emb_kernel(const float* __restrict__ emb) {
    int n = blockIdx.x;            // 512 blocks
    int t = threadIdx.x;           // 256 threads = D
    float e = emb[n * D + t];
    __shared__ float red[8];
    float s = e * e;
    #pragma unroll
    for (int o = 16; o > 0; o >>= 1) s += __shfl_xor_sync(0xffffffffu, s, o);
    if ((t & 31) == 0) red[t >> 5] = s;
    __syncthreads();
    if (t < 8) {
        float v = red[t];
        #pragma unroll
        for (int o = 4; o > 0; o >>= 1) v += __shfl_xor_sync(0x000000ffu, v, o);
        if (t == 0) red[0] = v;
    }
    __syncthreads();
    float inv = 1.0f / fmaxf(sqrtf(red[0]), 1e-12f);
    g_embn[n * D + t] = e * inv;
}

__global__ __launch_bounds__(256, 1)
void concept_kernel(const float* __restrict__ q,
                    const float* __restrict__ emb,
                    float* __restrict__ vec_out,
                    float* __restrict__ p_out) {
    extern __shared__ float sm[];
    float* S    = sm;                       // TM x SLD : sims -> exp(sims)
    float* At   = S  + TM * SLD;            // TM x ALD : q tile [m][k]
    float* Bt   = At + TM * ALD;            // TK x BLD : bank tile [k][n] / emb tile [k][d]
    float* rinv = Bt + TK * BLD;            // TM : 1/||q||
    float* rsum = rinv + TM;                // TM : 1/sum(exp)

    const int tid  = threadIdx.x;
    const int warp = tid >> 5, lane = tid & 31;
    const int tm   = tid >> 4, tn = tid & 15;       // 16 x 16 thread grid
    const size_t b0 = (size_t)blockIdx.x * TM;

    // ---- 1. per-query inverse L2 norm (coalesced, 8 rows per warp) ----
    #pragma unroll
    for (int mi = 0; mi < 8; mi++) {
        int m = warp * 8 + mi;
        const float* qr = q + (b0 + m) * D;
        float s = 0.f;
        #pragma unroll
        for (int i = 0; i < D / 32; i++) {
            float v = qr[lane + 32 * i];
            s += v * v;
        }
        #pragma unroll
        for (int o = 16; o > 0; o >>= 1) s += __shfl_xor_sync(0xffffffffu, s, o);
        if (lane == 0) rinv[m] = 1.0f / fmaxf(sqrtf(s), 1e-12f);
    }
    __syncthreads();

    // ---- 2. GEMM1: S = (Q/||q||) @ embn^T   (64 x 512) ----
    #pragma unroll 1
    for (int nc = 0; nc < NBANK / TN; nc++) {       // 4 n-chunks
        float acc[4][8];
        #pragma unroll
        for (int i = 0; i < 4; i++)
            #pragma unroll
            for (int j = 0; j < 8; j++) acc[i][j] = 0.f;

        #pragma unroll 1
        for (int kc = 0; kc < D / TK; kc++) {       // 8 k-chunks
            __syncthreads();
            // load A tile: 64x32 of q, row-major [m][k]
            #pragma unroll
            for (int r = 0; r < 2; r++) {
                int f = tid + r * 256;              // 512 float4 total
                int m = f >> 3, kq = (f & 7) << 2;
                float4 v = *(const float4*)(q + (b0 + m) * D + kc * TK + kq);
                *(float4*)(At + m * ALD + kq) = v;
            }
            // load B tile transposed: embn rows [nc*128..), cols [kc*32..) -> Bt[k][n]
            #pragma unroll
            for (int r = 0; r < 4; r++) {
                int f = tid + r * 256;              // 1024 float4 total
                int n = f >> 3, kq = (f & 7) << 2;
                float4 v = *(const float4*)(g_embn + (size_t)(nc * TN + n) * D + kc * TK + kq);
                Bt[(kq + 0) * BLD + n] = v.x;
                Bt[(kq + 1) * BLD + n] = v.y;
                Bt[(kq + 2) * BLD + n] = v.z;
                Bt[(kq + 3) * BLD + n] = v.w;
            }
            __syncthreads();
            #pragma unroll
            for (int kk = 0; kk < TK; kk++) {
                float a[4];
                #pragma unroll
                for (int i = 0; i < 4; i++) a[i] = At[(tm * 4 + i) * ALD + kk];
                float4 bv0 = *(const float4*)(Bt + kk * BLD + tn * 8);
                float4 bv1 = *(const float4*)(Bt + kk * BLD + tn * 8 + 4);
                float b[8] = {bv0.x, bv0.y, bv0.z, bv0.w, bv1.x, bv1.y, bv1.z, bv1.w};
                #pragma unroll
                for (int i = 0; i < 4; i++)
                    #pragma unroll
                    for (int j = 0; j < 8; j++) acc[i][j] = fmaf(a[i], b[j], acc[i][j]);
            }
        }
        // write scaled sims to S
        #pragma unroll
        for (int i = 0; i < 4; i++) {
            int m = tm * 4 + i;
            float sc = rinv[m];
            float* row = S + m * SLD + nc * TN + tn * 8;
            float4 o0 = make_float4(acc[i][0]*sc, acc[i][1]*sc, acc[i][2]*sc, acc[i][3]*sc);
            float4 o1 = make_float4(acc[i][4]*sc, acc[i][5]*sc, acc[i][6]*sc, acc[i][7]*sc);
            *(float4*)(row)     = o0;
            *(float4*)(row + 4) = o1;
        }
    }
    __syncthreads();

    // ---- 3. softmax over N (sims in [-1,1] -> no max subtraction needed) ----
    #pragma unroll 1
    for (int mi = 0; mi < 8; mi++) {
        int m = warp * 8 + mi;
        float* row = S + m * SLD;
        float e[16];
        float ssum = 0.f;
        #pragma unroll
        for (int i = 0; i < 16; i++) {
            float v = __expf(row[lane + 32 * i]);
            e[i] = v;
            ssum += v;
        }
        #pragma unroll
        for (int o = 16; o > 0; o >>= 1) ssum += __shfl_xor_sync(0xffffffffu, ssum, o);
        float inv = 1.0f / ssum;
        float* prow = p_out + (b0 + m) * NBANK;
        #pragma unroll
        for (int i = 0; i < 16; i++) {
            row[lane + 32 * i]  = e[i];          // keep exp values for GEMM2
            prow[lane + 32 * i] = e[i] * inv;    // coalesced p output
        }
        if (lane == 0) rsum[m] = inv;
    }
    __syncthreads();

    // ---- 4. GEMM2: vec = (exp(S) @ emb) * (1/sum)   (64 x 256) ----
    #pragma unroll 1
    for (int dc = 0; dc < D / TN; dc++) {           // 2 d-chunks
        float acc[4][8];
        #pragma unroll
        for (int i = 0; i < 4; i++)
            #pragma unroll
            for (int j = 0; j < 8; j++) acc[i][j] = 0.f;

        #pragma unroll 1
        for (int kc = 0; kc < NBANK / TK; kc++) {   // 16 k-chunks
            __syncthreads();
            // load B tile: emb rows [kc*32..), cols [dc*128..), natural layout [k][d]
            #pragma unroll
            for (int r = 0; r < 4; r++) {
                int f = tid + r * 256;              // 1024 float4
                int k = f >> 5, dq = (f & 31) << 2;
                float4 v = *(const float4*)(emb + (size_t)(kc * TK + k) * D + dc * TN + dq);
                *(float4*)(Bt + k * BLD + dq) = v;
            }
            __syncthreads();
            #pragma unroll
            for (int kk = 0; kk < TK; kk++) {
                float a[4];
                #pragma unroll
                for (int i = 0; i < 4; i++) a[i] = S[(tm * 4 + i) * SLD + kc * TK + kk];
                float4 bv0 = *(const float4*)(Bt + kk * BLD + tn * 8);
                float4 bv1 = *(const float4*)(Bt + kk * BLD + tn * 8 + 4);
                float b[8] = {bv0.x, bv0.y, bv0.z, bv0.w, bv1.x, bv1.y, bv1.z, bv1.w};
                #pragma unroll
                for (int i = 0; i < 4; i++)
                    #pragma unroll
                    for (int j = 0; j < 8; j++) acc[i][j] = fmaf(a[i], b[j], acc[i][j]);
            }
        }
        // write vec (coalesced float4)
        #pragma unroll
        for (int i = 0; i < 4; i++) {
            int m = tm * 4 + i;
            float sc = rsum[m];
            float* vrow = vec_out + (b0 + m) * D + dc * TN + tn * 8;
            float4 o0 = make_float4(acc[i][0]*sc, acc[i][1]*sc, acc[i][2]*sc, acc[i][3]*sc);
            float4 o1 = make_float4(acc[i][4]*sc, acc[i][5]*sc, acc[i][6]*sc, acc[i][7]*sc);
            *(float4*)(vrow)     = o0;
            *(float4*)(vrow + 4) = o1;
        }
    }
}

extern "C" void kernel_launch(void* const* d_in, const int* in_sizes, int n_in,
                              void* d_out, int out_size) {
    const float* q   = (const float*)d_in[0];   // (B, 256)
    const float* emb = (const float*)d_in[1];   // (512, 256)
    const int B = in_sizes[0] / D;

    float* vec_out = (float*)d_out;                         // (B, 256)
    float* p_out   = (float*)d_out + (size_t)B * D;         // (B, 512)

    cudaFuncSetAttribute(concept_kernel,
                         cudaFuncAttributeMaxDynamicSharedMemorySize, SMEM_BYTES);

    norm_emb_kernel<<<NBANK, D>>>(emb);
    concept_kernel<<<B / TM, 256, SMEM_BYTES>>>(q, emb, vec_out, p_out);
}